// round 6
// baseline (speedup 1.0000x reference)
#include <cuda_runtime.h>

// Analytic Clifford collapse (see R1/R2). All masks are COMPILE-TIME constants:
// the CNOT schedule is fixed, so Pi and the Pauli-string masks fold into the
// instruction stream. Block = 14 warps; warp w computes output qubit w for 32
// batch rows, so mask-dependent control flow is warp-uniform and constexpr.

#define NQ  14
#define BPB 32                        // batch rows per block (= lanes)
#define TPB (BPB * NQ)                // 448 threads = 14 warps

struct CMasks {
    unsigned x[NQ];
    unsigned z[NQ];
    int      ys[NQ];                  // Y-term sign: +1, -1, or 0
};

static constexpr unsigned cnot_ap(unsigned v, int c, int t) {
    unsigned cm = 1u << (NQ - 1 - c);
    unsigned tm = 1u << (NQ - 1 - t);
    return (v & cm) ? (v ^ tm) : v;
}

static constexpr CMasks make_masks() {
    CMasks mk{};
    int ctrl[28] = {}, tgt[28] = {};
    int k = 0;
    for (int step = 1; step <= 2; ++step)
        for (int c = 0; c < NQ; ++c) { ctrl[k] = c; tgt[k] = (c + step) % NQ; ++k; }

    unsigned picols[NQ] = {}, piinv[NQ] = {};
    for (int w = 0; w < NQ; ++w) {
        unsigned v = 1u << (NQ - 1 - w);
        for (int kk = 27; kk >= 0; --kk) v = cnot_ap(v, ctrl[kk], tgt[kk]);  // Pi (p27 innermost)
        picols[w] = v;
    }
    for (int q = 0; q < NQ; ++q) {
        unsigned v = 1u << (NQ - 1 - q);
        for (int kk = 0; kk < 28; ++kk) v = cnot_ap(v, ctrl[kk], tgt[kk]);   // Pi^{-1}
        piinv[q] = v;
    }
    for (int w = 0; w < NQ; ++w) {
        mk.x[w] = picols[w];
        unsigned z = 0;
        for (int q = 0; q < NQ; ++q)
            z |= ((piinv[q] >> (NQ - 1 - w)) & 1u) << (NQ - 1 - q);
        mk.z[w] = z;
        unsigned a = mk.x[w] & mk.z[w];
        int pc = 0;
        for (int q = 0; q < NQ; ++q) pc += (a >> q) & 1u;
        // Y-string = (-i)^pc * P (P real);  Re(i * (-i)^pc) = +1 (pc%4==1), -1 (pc%4==3), 0 (even)
        mk.ys[w] = (pc % 4 == 1) ? 1 : (pc % 4 == 3) ? -1 : 0;
    }
    return mk;
}

static constexpr CMasks MK = make_masks();

// Fully-unrolled per-w product with compile-time masks. Dead factors and the
// whole PY chain (when YS==0) are eliminated at compile time.
template<unsigned XM, unsigned ZM, int YS>
__device__ __forceinline__ float compute_out(const float4 (*sF)[BPB], int lane,
                                             float c0, float c1, float c2)
{
    float EZ = 1.0f, EX = 1.0f, PY = 1.0f;
    #pragma unroll
    for (int q = 0; q < NQ; ++q) {
        const bool xb = (XM >> (NQ - 1 - q)) & 1u;   // compile-time after unroll
        const bool zb = (ZM >> (NQ - 1 - q)) & 1u;
        if (xb || zb) {
            float4 f = sF[q][lane];
            if (zb) EZ *= f.y;
            if (xb) EX *= f.x;
            if (YS != 0) {
                if (xb && zb)      PY *= f.z;
                else if (xb)       PY *= f.x;
                else /* zb */      PY *= f.y;
            }
        }
    }
    float r = c0 * EZ + c1 * EX;
    if (YS > 0)      r += c2 * PY;
    else if (YS < 0) r -= c2 * PY;
    return r;
}

__global__ __launch_bounds__(TPB)
void qulinear_pauli_kernel(const float* __restrict__ x,
                           const float* __restrict__ u3,
                           float* __restrict__ out,
                           int B)
{
    const int t    = threadIdx.x;
    const int lane = t & 31;          // batch row within block
    const int wid  = t >> 5;          // output qubit (warp-uniform)
    const int b    = blockIdx.x * BPB + lane;
    const bool active = (b < B);

    __shared__ float4 sF[NQ][BPB];    // [qubit][batch row] = {Xf, Zf, CW, 0}

    // Phase 1: per-(row, qubit=wid) Bloch factors. ry=atan(x), rz=atan(x^2):
    //   sin(atan u)=u*rsqrt(1+u^2), cos(atan u)=rsqrt(1+u^2)  -> no trig.
    if (active) {
        float xv = x[b * NQ + wid];
        float x2 = xv * xv;
        float r1 = rsqrtf(1.0f + x2);         // cos(ry)
        float r2 = rsqrtf(1.0f + x2 * x2);    // cos(rz)
        float4 f;
        f.x = r1 * r2;                        // <X>
        f.y = -xv * r1;                       // <Z>
        f.z = x2 * r1 * r2;                   // CW, <XZ> = -i*CW
        f.w = 0.0f;
        sF[wid][lane] = f;                    // contiguous 512B per warp
    }

    // Per-warp coefficients: lane 0 does the trig for this warp's w, broadcast.
    //   U3^dag Z U3 = cos(th) Z - sin(th)cos(lam) X + sin(th)sin(lam) Y
    float c0 = 0.0f, c1 = 0.0f, c2 = 0.0f;
    if (lane == 0) {
        float th  = u3[wid * 3 + 0];
        float lam = u3[wid * 3 + 2];
        float sth, cth, sl, cl;
        __sincosf(th,  &sth, &cth);
        __sincosf(lam, &sl,  &cl);
        c0 = cth;
        c1 = -sth * cl;
        c2 = sth * sl;                        // sign handled by YS template arg
    }
    c0 = __shfl_sync(0xffffffffu, c0, 0);
    c1 = __shfl_sync(0xffffffffu, c1, 0);
    c2 = __shfl_sync(0xffffffffu, c2, 0);

    __syncthreads();

    // Phase 2: warp-uniform dispatch to fully-folded product code.
    float r;
    switch (wid) {
#define QCASE(W) case W: r = compute_out<MK.x[W], MK.z[W], MK.ys[W]>(sF, lane, c0, c1, c2); break;
        QCASE(0)  QCASE(1)  QCASE(2)  QCASE(3)  QCASE(4)  QCASE(5)  QCASE(6)
        QCASE(7)  QCASE(8)  QCASE(9)  QCASE(10) QCASE(11) QCASE(12) QCASE(13)
#undef QCASE
        default: r = 0.0f; break;
    }

    if (active)
        out[b * NQ + wid] = r;
}

extern "C" void kernel_launch(void* const* d_in, const int* in_sizes, int n_in,
                              void* d_out, int out_size)
{
    const float* x  = (const float*)d_in[0];   // [B, 14]
    const float* u3 = (const float*)d_in[1];   // [14, 3]
    float* out = (float*)d_out;                // [B, 14]

    int B = in_sizes[0] / NQ;
    int grid = (B + BPB - 1) / BPB;
    qulinear_pauli_kernel<<<grid, TPB>>>(x, u3, out, B);
}

// round 8
// speedup vs baseline: 1.0435x; 1.0435x over previous
#include <cuda_runtime.h>

// Analytic Clifford collapse (see R1/R2). R6 lesson: this problem is
// latency-bound, not issue-bound — barriers / shuffles / switch dispatch cost
// more than the ALU they save. So: ONE THREAD PER BATCH ROW, all 14 outputs in
// registers. No SMEM, no __syncthreads, no shuffles, no branches. Masks are
// function-local constexpr (R7 fix: host-namespace constexpr objects can't be
// ODR-used from device code); everything folds after full unroll.

#define NQ 14

struct CMasks {
    unsigned x[NQ];
    unsigned z[NQ];
    int      ys[NQ];                  // Y-term sign: +1, -1, or 0
};

__host__ __device__ static constexpr unsigned cnot_ap(unsigned v, int c, int t) {
    unsigned cm = 1u << (NQ - 1 - c);
    unsigned tm = 1u << (NQ - 1 - t);
    return (v & cm) ? (v ^ tm) : v;
}

__host__ __device__ static constexpr CMasks make_masks() {
    CMasks mk{};
    int ctrl[28] = {}, tgt[28] = {};
    int k = 0;
    for (int step = 1; step <= 2; ++step)
        for (int c = 0; c < NQ; ++c) { ctrl[k] = c; tgt[k] = (c + step) % NQ; ++k; }

    unsigned picols[NQ] = {}, piinv[NQ] = {};
    for (int w = 0; w < NQ; ++w) {
        unsigned v = 1u << (NQ - 1 - w);
        for (int kk = 27; kk >= 0; --kk) v = cnot_ap(v, ctrl[kk], tgt[kk]);  // Pi (p27 innermost)
        picols[w] = v;
    }
    for (int q = 0; q < NQ; ++q) {
        unsigned v = 1u << (NQ - 1 - q);
        for (int kk = 0; kk < 28; ++kk) v = cnot_ap(v, ctrl[kk], tgt[kk]);   // Pi^{-1}
        piinv[q] = v;
    }
    for (int w = 0; w < NQ; ++w) {
        mk.x[w] = picols[w];
        unsigned z = 0;
        for (int q = 0; q < NQ; ++q)
            z |= ((piinv[q] >> (NQ - 1 - w)) & 1u) << (NQ - 1 - q);
        mk.z[w] = z;
        unsigned a = mk.x[w] & mk.z[w];
        int pc = 0;
        for (int q = 0; q < NQ; ++q) pc += (a >> q) & 1u;
        // Y-string = (-i)^pc * P (P real); Re(i*(-i)^pc) = +1 (pc%4==1), -1 (pc%4==3), 0 (even)
        mk.ys[w] = (pc % 4 == 1) ? 1 : (pc % 4 == 3) ? -1 : 0;
    }
    return mk;
}

#define TPB 64    // 2 warps/block, 32 blocks -> <=1 warp per SMSP, no MUFU contention

__global__ __launch_bounds__(TPB, 1)
void qulinear_reg_kernel(const float* __restrict__ x,
                         const float* __restrict__ u3,
                         float* __restrict__ out,
                         int B)
{
    constexpr CMasks MK = make_masks();      // compile-time, folds after unroll

    const int b = blockIdx.x * TPB + threadIdx.x;
    if (b >= B) return;

    // ---- Load this row's 14 inputs (56B, 8B-aligned) as 7x float2, MLP=7 ----
    float xv[NQ];
    {
        const float2* xr = reinterpret_cast<const float2*>(x + b * NQ);
        #pragma unroll
        for (int i = 0; i < NQ / 2; ++i) {
            float2 v = xr[i];
            xv[2 * i]     = v.x;
            xv[2 * i + 1] = v.y;
        }
    }

    // ---- u3 params (grid-uniform; L1/L2-hit loads, batched) ----
    float th[NQ], lam[NQ];
    #pragma unroll
    for (int w = 0; w < NQ; ++w) {
        th[w]  = u3[w * 3 + 0];
        lam[w] = u3[w * 3 + 2];
    }

    // ---- Per-qubit Bloch factors. ry=atan(x), rz=atan(x^2):
    //      sin(atan u)=u*rsqrt(1+u^2), cos(atan u)=rsqrt(1+u^2) -> no trig. ----
    float Xf[NQ], Zf[NQ], CW[NQ];
    #pragma unroll
    for (int q = 0; q < NQ; ++q) {
        float x2 = xv[q] * xv[q];
        float r1 = rsqrtf(1.0f + x2);        // cos(ry)
        float r2 = rsqrtf(1.0f + x2 * x2);   // cos(rz)
        Xf[q] = r1 * r2;                     // <X>
        Zf[q] = -xv[q] * r1;                 // <Z>
        CW[q] = x2 * Xf[q];                  // <XZ> = -i*CW
    }

    // ---- 14 outputs: straight-line products with compile-time masks ----
    //   U3^dag Z U3 = cos(th) Z - sin(th)cos(lam) X + sin(th)sin(lam) Y
    #pragma unroll
    for (int w = 0; w < NQ; ++w) {
        float sth, cth, sl, cl;
        __sincosf(th[w],  &sth, &cth);
        __sincosf(lam[w], &sl,  &cl);
        const float c0 = cth;
        const float c1 = -sth * cl;
        const float c2 = sth * sl;

        const unsigned xm = MK.x[w];         // constexpr -> folds after unroll
        const unsigned zm = MK.z[w];
        const int      ys = MK.ys[w];

        float EZ = 1.0f, EX = 1.0f, PY = 1.0f;
        #pragma unroll
        for (int q = 0; q < NQ; ++q) {
            const bool xb = (xm >> (NQ - 1 - q)) & 1u;
            const bool zb = (zm >> (NQ - 1 - q)) & 1u;
            if (zb) EZ *= Zf[q];
            if (xb) EX *= Xf[q];
            if (ys != 0) {
                if (xb && zb)      PY *= CW[q];
                else if (xb)       PY *= Xf[q];
                else if (zb)       PY *= Zf[q];
            }
        }
        float r = c0 * EZ + c1 * EX;
        if (ys > 0)      r += c2 * PY;
        else if (ys < 0) r -= c2 * PY;

        out[b * NQ + w] = r;                 // contiguous 56B per thread
    }
}

extern "C" void kernel_launch(void* const* d_in, const int* in_sizes, int n_in,
                              void* d_out, int out_size)
{
    const float* x  = (const float*)d_in[0];   // [B, 14]
    const float* u3 = (const float*)d_in[1];   // [14, 3]
    float* out = (float*)d_out;                // [B, 14]

    int B = in_sizes[0] / NQ;
    int grid = (B + TPB - 1) / TPB;            // 32 blocks for B=2048
    qulinear_reg_kernel<<<grid, TPB>>>(x, u3, out, B);
}

// round 15
// speedup vs baseline: 1.1250x; 1.0781x over previous
#include <cuda_runtime.h>

// Analytic Clifford collapse (R1/R2). R8 post-mortem: body is FMA-pipe-bound
// (~420 fma slots/thread @ rt2 = ~840cy, 1 warp/SMSP). R9: split each row's 14
// outputs across 2 threads (warp-uniform halves) and shrink PY via the ratio
// trick PY = EZ*EX*prod R,  R[q] = (1+x^2)*Zf[q]. Still zero SMEM / zero
// barriers / zero shuffles (R6 lesson: sync constructs cost more than ALU).

#define NQ 14

struct CMasks {
    unsigned x[NQ];
    unsigned z[NQ];
    int      ys[NQ];                  // Y-term sign: +1, -1, or 0
};

__host__ __device__ static constexpr unsigned cnot_ap(unsigned v, int c, int t) {
    unsigned cm = 1u << (NQ - 1 - c);
    unsigned tm = 1u << (NQ - 1 - t);
    return (v & cm) ? (v ^ tm) : v;
}

__host__ __device__ static constexpr CMasks make_masks() {
    CMasks mk{};
    int ctrl[28] = {}, tgt[28] = {};
    int k = 0;
    for (int step = 1; step <= 2; ++step)
        for (int c = 0; c < NQ; ++c) { ctrl[k] = c; tgt[k] = (c + step) % NQ; ++k; }

    unsigned picols[NQ] = {}, piinv[NQ] = {};
    for (int w = 0; w < NQ; ++w) {
        unsigned v = 1u << (NQ - 1 - w);
        for (int kk = 27; kk >= 0; --kk) v = cnot_ap(v, ctrl[kk], tgt[kk]);  // Pi (p27 innermost)
        picols[w] = v;
    }
    for (int q = 0; q < NQ; ++q) {
        unsigned v = 1u << (NQ - 1 - q);
        for (int kk = 0; kk < 28; ++kk) v = cnot_ap(v, ctrl[kk], tgt[kk]);   // Pi^{-1}
        piinv[q] = v;
    }
    for (int w = 0; w < NQ; ++w) {
        mk.x[w] = picols[w];
        unsigned z = 0;
        for (int q = 0; q < NQ; ++q)
            z |= ((piinv[q] >> (NQ - 1 - w)) & 1u) << (NQ - 1 - q);
        mk.z[w] = z;
        unsigned a = mk.x[w] & mk.z[w];
        int pc = 0;
        for (int q = 0; q < NQ; ++q) pc += (a >> q) & 1u;
        // Y-string = (-i)^pc * P; Re(i*(-i)^pc) = +1 (pc%4==1), -1 (pc%4==3), 0 (even)
        mk.ys[w] = (pc % 4 == 1) ? 1 : (pc % 4 == 3) ? -1 : 0;
    }
    return mk;
}

// Outputs [W0, W0+7) for one batch row; masks fold at compile time.
//   U3^dag Z U3 = cos(th) Z - sin(th)cos(lam) X + sin(th)sin(lam) Y
//   PY = EZ * EX * prod_{q in x&z} R[q],  R[q] = (1+x^2)*Zf[q]   (exact)
template<int W0>
__device__ __forceinline__ void compute7(const float* __restrict__ u3,
                                         const float Xf[NQ], const float Zf[NQ],
                                         const float Rf[NQ], float res[7])
{
    constexpr CMasks MK = make_masks();

    // Batch the u3 loads for MLP (L2-hit latency overlapped).
    float th7[7], lm7[7];
    #pragma unroll
    for (int i = 0; i < 7; ++i) {
        th7[i] = u3[(W0 + i) * 3 + 0];
        lm7[i] = u3[(W0 + i) * 3 + 2];
    }

    #pragma unroll
    for (int i = 0; i < 7; ++i) {
        const int w = W0 + i;
        float sth, cth, sl, cl;
        __sincosf(th7[i], &sth, &cth);
        __sincosf(lm7[i], &sl,  &cl);

        const unsigned xm = MK.x[w];        // constexpr -> folds after unroll
        const unsigned zm = MK.z[w];
        const int      ys = MK.ys[w];

        float EZ = 1.0f, EX = 1.0f;
        #pragma unroll
        for (int q = 0; q < NQ; ++q) {
            if ((zm >> (NQ - 1 - q)) & 1u) EZ *= Zf[q];
            if ((xm >> (NQ - 1 - q)) & 1u) EX *= Xf[q];
        }

        float r = cth * EZ - (sth * cl) * EX;
        if (ys != 0) {
            float PY = EZ * EX;
            #pragma unroll
            for (int q = 0; q < NQ; ++q)
                if (((xm & zm) >> (NQ - 1 - q)) & 1u) PY *= Rf[q];
            if (ys > 0) r += (sth * sl) * PY;
            else        r -= (sth * sl) * PY;
        }
        res[i] = r;
    }
}

#define TPB 64   // 2 warps: warp 0 -> outputs 0-6, warp 1 -> outputs 7-13, same 32 rows

__global__ __launch_bounds__(TPB, 1)
void qulinear_split2_kernel(const float* __restrict__ x,
                            const float* __restrict__ u3,
                            float* __restrict__ out,
                            int B)
{
    const int lane = threadIdx.x & 31;    // batch row within block
    const int half = threadIdx.x >> 5;    // 0: outputs 0-6, 1: outputs 7-13 (warp-uniform)
    const int b    = blockIdx.x * 32 + lane;
    if (b >= B) return;

    // ---- Load this row's 14 inputs as 7x float2 (56B, 8B-aligned), MLP=7 ----
    float xv[NQ];
    {
        const float2* xr = reinterpret_cast<const float2*>(x + b * NQ);
        #pragma unroll
        for (int i = 0; i < NQ / 2; ++i) {
            float2 v = xr[i];
            xv[2 * i]     = v.x;
            xv[2 * i + 1] = v.y;
        }
    }

    // ---- Per-qubit Bloch factors. ry=atan(x), rz=atan(x^2):
    //      sin(atan u)=u*rsqrt(1+u^2), cos(atan u)=rsqrt(1+u^2). ----
    float Xf[NQ], Zf[NQ], Rf[NQ];
    #pragma unroll
    for (int q = 0; q < NQ; ++q) {
        float x2 = xv[q] * xv[q];
        float a  = 1.0f + x2;
        float r1 = rsqrtf(a);                // cos(ry)
        float r2 = rsqrtf(1.0f + x2 * x2);   // cos(rz)
        Xf[q] = r1 * r2;                     // <X>
        Zf[q] = -xv[q] * r1;                 // <Z>
        Rf[q] = a * Zf[q];                   // CW/(Xf*Zf), exact (0 when x=0)
    }

    // ---- 7 outputs for this half (warp-uniform branch, both straight-line) ----
    float res[7];
    if (half == 0) compute7<0>(u3, Xf, Zf, Rf, res);
    else           compute7<7>(u3, Xf, Zf, Rf, res);

    float* op = out + b * NQ + half * 7;
    #pragma unroll
    for (int i = 0; i < 7; ++i)
        op[i] = res[i];
}

extern "C" void kernel_launch(void* const* d_in, const int* in_sizes, int n_in,
                              void* d_out, int out_size)
{
    const float* x  = (const float*)d_in[0];   // [B, 14]
    const float* u3 = (const float*)d_in[1];   // [14, 3]
    float* out = (float*)d_out;                // [B, 14]

    int B = in_sizes[0] / NQ;
    int grid = (B + 31) / 32;                  // 64 blocks for B=2048
    qulinear_split2_kernel<<<grid, TPB>>>(x, u3, out, B);
}